// round 15
// baseline (speedup 1.0000x reference)
#include <cuda_runtime.h>

#define N_ENTITY 100000
#define DD 128
#define HIDSZ 256
#define N_REL 48
#define NB 8
#define NEDGE 1000000
#define N_POS 1024
#define CAP (1 << 17)
#define ZMAX (N_POS * N_REL)
#define TILE 4
#define KTOT 1152           // 128 root + 8*128 bases rows
#define NSLICE 16
#define KSLICE (KTOT / NSLICE)   // 72 rows
#define GRID 296
#define NTH 512

#define PACK_DUP(out, f) \
    asm("mov.b64 %0, {%1, %1};" : "=l"(out) : "r"(__float_as_uint(f)))
#define FMA2(acc, a, b) \
    asm("fma.rn.f32x2 %0, %1, %2, %0;" : "+l"(acc) : "l"(a), "l"(b))

// ---- device scratch (no allocation allowed) ----
__device__ int   g_map[N_ENTITY];
__device__ int   g_deg[N_POS * N_REL];
__device__ float g_s[N_POS * N_REL * DD];
__device__ float g_w[KTOT * DD];     // root ‖ bases, contiguous
__device__ int4  g_ce[CAP];
__device__ int   g_cnt;
__device__ int   g_zlist[ZMAX];
__device__ int   g_zcnt;
__device__ int   g_bar_count;
__device__ volatile int g_bar_gen;

__device__ __forceinline__ void grid_bar() {
    __syncthreads();
    if (threadIdx.x == 0) {
        int gen = g_bar_gen;
        __threadfence();
        if (atomicAdd(&g_bar_count, 1) == (int)gridDim.x - 1) {
            g_bar_count = 0;
            __threadfence();
            g_bar_gen = gen + 1;
        } else {
            while (g_bar_gen == gen) { }
        }
        __threadfence();
    }
    __syncthreads();
}

// ==== Single persistent kernel: prep (P0..P4) + fused final pipeline ====
__global__ __launch_bounds__(NTH, 2)
void k_all(const float* __restrict__ x,
           const float* __restrict__ bases,
           const float* __restrict__ comp,
           const float* __restrict__ root,
           const float* __restrict__ bias,
           const float* __restrict__ w1, const float* __restrict__ b1,
           const float* __restrict__ w2, const float* __restrict__ b2,
           const float* __restrict__ wp, const float* __restrict__ bp,
           const int* __restrict__ ei, const int* __restrict__ et,
           const int* __restrict__ ids, float* __restrict__ out) {
    const int tid  = threadIdx.x;
    const int gtid = blockIdx.x * NTH + tid;
    const int NT   = gridDim.x * NTH;
    const int lane = tid & 31;

    // ---- P0: init + weight concat ----
    for (int i = gtid; i < N_ENTITY; i += NT) g_map[i] = 0x7fffffff;
    for (int i = gtid; i < N_POS * N_REL; i += NT) g_deg[i] = 0;
    for (int i = gtid; i < KTOT * DD; i += NT)
        g_w[i] = (i < DD * DD) ? root[i] : bases[i - DD * DD];
    if (gtid == 0) { g_cnt = 0; g_zcnt = 0; }
    grid_bar();

    // ---- P1: scatter (min position canonical) ----
    if (gtid < N_POS) atomicMin(&g_map[ids[gtid]], gtid);
    grid_bar();

    // ---- P2: edge scan with warp-aggregated compaction atomics ----
    {
        const int NQUAD = NEDGE / 4;
        const int NITER = (NQUAD + NT - 1) / NT;   // 2
        for (int it = 0; it < NITER; ++it) {
            int t = gtid + it * NT;
            bool valid = t < NQUAD;
            int4 dst4 = valid ? reinterpret_cast<const int4*>(ei + NEDGE)[t]
                              : make_int4(0, 0, 0, 0);
            int ds[4] = {dst4.x, dst4.y, dst4.z, dst4.w};
#pragma unroll
            for (int q = 0; q < 4; ++q) {
                int slot = valid ? g_map[ds[q]] : 0x7fffffff;
                bool hit = slot < N_POS;
                unsigned m = __ballot_sync(0xffffffffu, hit);
                if (hit) {
                    int e = t * 4 + q;
                    int rel = __ldg(&et[e]);
                    int row = slot * N_REL + rel;
                    int old = atomicAdd(&g_deg[row], 1);
                    if (old == 1) {
                        int zp = atomicAdd(&g_zcnt, 1);
                        if (zp < ZMAX) g_zlist[zp] = row;
                    }
                    int leader = __ffs(m) - 1;
                    int rank = __popc(m & ((1u << lane) - 1u));
                    int base = 0;
                    if (lane == leader) base = atomicAdd(&g_cnt, __popc(m));
                    base = __shfl_sync(m, base, leader);
                    int p = base + rank;
                    if (p < CAP) g_ce[p] = make_int4(__ldg(&ei[e]), slot, rel, 0);
                }
            }
        }
    }
    grid_bar();

    // ---- P3: zero deg>=2 rows ----
    {
        int warp = gtid >> 5, nw = NT >> 5;
        int nz = *(volatile int*)&g_zcnt; if (nz > ZMAX) nz = ZMAX;
        float4 z = make_float4(0.f, 0.f, 0.f, 0.f);
        for (int i = warp; i < nz; i += nw) {
            int row = g_zlist[i];
            reinterpret_cast<float4*>(g_s + (size_t)row * DD)[lane] = z;
        }
    }
    grid_bar();

    // ---- P4: accumulate edges ----
    {
        int warp = gtid >> 5, nw = NT >> 5;
        int cnt = *(volatile int*)&g_cnt; if (cnt > CAP) cnt = CAP;
        for (int i = warp; i < cnt; i += nw) {
            int4 ce = g_ce[i];
            int row = ce.y * N_REL + ce.z;
            int dg = g_deg[row];
            float4 xv = reinterpret_cast<const float4*>(x + (long)ce.x * DD)[lane];
            float* sp = &g_s[(size_t)row * DD + lane * 4];
            if (dg == 1) {
                *reinterpret_cast<float4*>(sp) = xv;
            } else {
                atomicAdd(sp + 0, xv.x);
                atomicAdd(sp + 1, xv.y);
                atomicAdd(sp + 2, xv.z);
                atomicAdd(sp + 3, xv.w);
            }
        }
    }
    grid_bar();

    // ==== Final fused pipeline: blocks 0..255 handle TILE=4 positions each ====
    if (blockIdx.x >= N_POS / TILE) return;

    extern __shared__ float sm[];
    float* aT    = sm;                     // [KTOT][4] = 4608 floats
    float* compS = aT + KTOT * TILE;       // 384
    float* normS = compS + N_REL * NB;     // 192
    float* hb    = normS + TILE * N_REL;   // 512
    float* zb    = hb + TILE * DD;         // 256
    float* red   = zb + TILE * 64;         // 8192
    int*  canon  = (int*)(red + 8192);     // 4 ints

    const int pbase = blockIdx.x * TILE;

    if (tid < TILE) canon[tid] = __ldcg(&g_map[ids[pbase + tid]]);
    {
        int p = tid >> 7, d = tid & 127;
        aT[d * TILE + p] = x[(long)ids[pbase + p] * DD + d];
    }
    if (tid < N_REL * NB) compS[tid] = comp[tid];
    __syncthreads();
    if (tid < TILE * N_REL) {
        int p = tid / N_REL, r = tid % N_REL;
        int dg = __ldcg(&g_deg[canon[p] * N_REL + r]);
        normS[tid] = dg > 0 ? 1.0f / (float)dg : 0.0f;
    }
    __syncthreads();

    // phase 2: vv -> aT[(k+1)*128 + d][pp], packed f32x2 (g_s via __ldcg)
    {
        const int pp = tid >> 7;
        const int d  = tid & 127;
        const float* srow = &g_s[(size_t)canon[pp] * N_REL * DD + d];
        unsigned long long acc2[4] = {0ull, 0ull, 0ull, 0ull};
        for (int r = 0; r < N_REL; ++r) {
            float nm = normS[pp * N_REL + r];
            if (nm != 0.0f) {
                float sv = __ldcg(srow + r * DD) * nm;
                unsigned long long sv2;
                PACK_DUP(sv2, sv);
                const unsigned long long* cp =
                    reinterpret_cast<const unsigned long long*>(compS + r * NB);
#pragma unroll
                for (int k2 = 0; k2 < 4; ++k2) FMA2(acc2[k2], sv2, cp[k2]);
            }
        }
#pragma unroll
        for (int k2 = 0; k2 < 4; ++k2) {
            unsigned int lo, hi;
            asm("mov.b64 {%0, %1}, %2;" : "=r"(lo), "=r"(hi) : "l"(acc2[k2]));
            aT[((2 * k2 + 1) * DD + d) * TILE + pp] = __uint_as_float(lo);
            aT[((2 * k2 + 2) * DD + d) * TILE + pp] = __uint_as_float(hi);
        }
    }
    __syncthreads();

    // phase 3: GEMM, 16 K-slices x 32 lanes, 4pos x 4col, FFMA2
    {
        const int kh = tid >> 5;
        const int c0 = (tid & 31) * 4;
        unsigned long long acc2[8];
#pragma unroll
        for (int i = 0; i < 8; ++i) acc2[i] = 0ull;

        const int r0 = kh * KSLICE;
        const float* Wb = g_w + (size_t)r0 * DD + c0;
        const float* Ab = aT + r0 * TILE;

        for (int ch = 0; ch < KSLICE; ch += 4) {
            ulonglong2 w[4];
#pragma unroll
            for (int t = 0; t < 4; ++t)
                w[t] = *reinterpret_cast<const ulonglong2*>(Wb + (size_t)(ch + t) * DD);
#pragma unroll
            for (int t = 0; t < 4; ++t) {
                float4 a = *reinterpret_cast<const float4*>(Ab + (ch + t) * TILE);
                unsigned long long ax, ay, az, aw;
                PACK_DUP(ax, a.x);
                PACK_DUP(ay, a.y);
                PACK_DUP(az, a.z);
                PACK_DUP(aw, a.w);
                FMA2(acc2[0], ax, w[t].x); FMA2(acc2[1], ax, w[t].y);
                FMA2(acc2[2], ay, w[t].x); FMA2(acc2[3], ay, w[t].y);
                FMA2(acc2[4], az, w[t].x); FMA2(acc2[5], az, w[t].y);
                FMA2(acc2[6], aw, w[t].x); FMA2(acc2[7], aw, w[t].y);
            }
        }
#pragma unroll
        for (int p = 0; p < TILE; ++p) {
            ulonglong2 v;
            v.x = acc2[p * 2]; v.y = acc2[p * 2 + 1];
            *reinterpret_cast<ulonglong2*>(red + kh * (TILE * DD) + p * DD + c0) = v;
        }
    }
    __syncthreads();

    // reduce 16 partials + bias + residual -> hb[pos][d]
    {
        int p = tid >> 7, d = tid & 127;
        float s = bias[d] + aT[d * TILE + p];
#pragma unroll
        for (int k = 0; k < NSLICE; ++k) s += red[k * (TILE * DD) + tid];
        hb[tid] = s;
    }
    __syncthreads();

    // stage w1
    {
        const float4* src = reinterpret_cast<const float4*>(w1);
        float4* dst = reinterpret_cast<float4*>(red);
#pragma unroll
        for (int t = 0; t < 4; ++t) dst[tid + t * 512] = src[tid + t * 512];
    }
    __syncthreads();

    // phase 5: zb[p][c] = relu(hb[p] @ w1 + b1)
    if (tid < TILE * 64) {
        int p = tid >> 6, c = tid & 63;
        float acc = b1[c];
        const float* wcol = red + c;
        const float4* h4 = reinterpret_cast<const float4*>(hb + p * DD);
#pragma unroll 4
        for (int j4 = 0; j4 < DD / 4; ++j4) {
            float w0 = wcol[(j4 * 4 + 0) * 64];
            float w1v = wcol[(j4 * 4 + 1) * 64];
            float w2v = wcol[(j4 * 4 + 2) * 64];
            float w3v = wcol[(j4 * 4 + 3) * 64];
            float4 h = h4[j4];
            acc += h.x * w0 + h.y * w1v + h.z * w2v + h.w * w3v;
        }
        zb[p * 64 + c] = fmaxf(acc, 0.0f);
    }
    __syncthreads();

    // stage w2
    {
        const float4* src = reinterpret_cast<const float4*>(w2);
        float4* dst = reinterpret_cast<float4*>(red);
#pragma unroll
        for (int t = 0; t < 4; ++t) dst[tid + t * 512] = src[tid + t * 512];
    }
    __syncthreads();

    // phase 6: hb[p][dd] += zb[p] @ w2 + b2
    {
        int p = tid >> 7, dd2 = tid & 127;
        float acc = b2[dd2] + hb[tid];
        const float* wcol = red + dd2;
        const float4* z4 = reinterpret_cast<const float4*>(zb + p * 64);
#pragma unroll 4
        for (int c4 = 0; c4 < 16; ++c4) {
            float w0 = wcol[(c4 * 4 + 0) * DD];
            float w1v = wcol[(c4 * 4 + 1) * DD];
            float w2v = wcol[(c4 * 4 + 2) * DD];
            float w3v = wcol[(c4 * 4 + 3) * DD];
            float4 z = z4[c4];
            acc += z.x * w0 + z.y * w1v + z.z * w2v + z.w * w3v;
        }
        hb[tid] = acc;
    }
    __syncthreads();

    // phase 7: out = hb @ wp + bp (1024 outputs, 2 pos/thread)
    {
        int o = tid & 255, ph = tid >> 8;
        int p0 = ph * 2;
        float b = bp[o];
        float acc0 = b, acc1 = b;
        const float* wcol = wp + o;
        const float4* h0 = reinterpret_cast<const float4*>(hb + p0 * DD);
        const float4* h1 = reinterpret_cast<const float4*>(hb + (p0 + 1) * DD);
#pragma unroll 4
        for (int j4 = 0; j4 < DD / 4; ++j4) {
            float w0 = wcol[(size_t)(j4 * 4 + 0) * HIDSZ];
            float w1v = wcol[(size_t)(j4 * 4 + 1) * HIDSZ];
            float w2v = wcol[(size_t)(j4 * 4 + 2) * HIDSZ];
            float w3v = wcol[(size_t)(j4 * 4 + 3) * HIDSZ];
            float4 a = h0[j4], c = h1[j4];
            acc0 += a.x * w0 + a.y * w1v + a.z * w2v + a.w * w3v;
            acc1 += c.x * w0 + c.y * w1v + c.z * w2v + c.w * w3v;
        }
        out[((long)(pbase + p0)) * HIDSZ + o] = acc0;
        out[((long)(pbase + p0 + 1)) * HIDSZ + o] = acc1;
    }
}

extern "C" void kernel_launch(void* const* d_in, const int* in_sizes, int n_in,
                              void* d_out, int out_size) {
    const float* node_embeds = (const float*)d_in[0];
    const float* bases       = (const float*)d_in[1];
    const float* comp        = (const float*)d_in[2];
    const float* root        = (const float*)d_in[3];
    const float* bias        = (const float*)d_in[4];
    const float* w1          = (const float*)d_in[5];
    const float* b1          = (const float*)d_in[6];
    const float* w2          = (const float*)d_in[7];
    const float* b2          = (const float*)d_in[8];
    const float* wp          = (const float*)d_in[9];
    const float* bp          = (const float*)d_in[10];
    const int*   edge_index  = (const int*)d_in[11];
    const int*   edge_type   = (const int*)d_in[12];
    const int*   entity_ids  = (const int*)d_in[13];
    float* out = (float*)d_out;

    const int smem_bytes = (KTOT * TILE + N_REL * NB + TILE * N_REL +
                            TILE * DD + TILE * 64 + 8192) * 4 + TILE * 4;
    cudaFuncSetAttribute(k_all, cudaFuncAttributeMaxDynamicSharedMemorySize, smem_bytes);

    k_all<<<GRID, NTH, smem_bytes>>>(node_embeds, bases, comp, root, bias,
                                     w1, b1, w2, b2, wp, bp,
                                     edge_index, edge_type, entity_ids, out);
    (void)in_sizes; (void)n_in; (void)out_size;
}

// round 16
// speedup vs baseline: 1.0387x; 1.0387x over previous
#include <cuda_runtime.h>

#define N_ENTITY 100000
#define DD 128
#define HIDSZ 256
#define N_REL 48
#define NB 8
#define NEDGE 1000000
#define N_POS 1024
#define CAP (1 << 17)
#define ZMAX (N_POS * N_REL)
#define TILE 4
#define KTOT 1152           // 128 root + 8*128 bases rows
#define NSLICE 16
#define KSLICE (KTOT / NSLICE)   // 72 rows
#define GRID 296
#define NTH 512

#define PACK_DUP(out, f) \
    asm("mov.b64 %0, {%1, %1};" : "=l"(out) : "r"(__float_as_uint(f)))
#define FMA2(acc, a, b) \
    asm("fma.rn.f32x2 %0, %1, %2, %0;" : "+l"(acc) : "l"(a), "l"(b))

// ---- device scratch (no allocation allowed) ----
__device__ int   g_map[N_ENTITY];
__device__ int   g_deg[N_POS * N_REL];
__device__ float g_s[N_POS * N_REL * DD];
__device__ float g_w[KTOT * DD];     // root ‖ bases, contiguous
__device__ int4  g_ce[CAP];
__device__ int   g_cnt;
__device__ int   g_zlist[ZMAX];
__device__ int   g_zcnt;
__device__ int   g_bar_count;
__device__ volatile int g_bar_gen;

__device__ __forceinline__ void grid_bar() {
    __syncthreads();
    if (threadIdx.x == 0) {
        int gen = g_bar_gen;
        __threadfence();
        if (atomicAdd(&g_bar_count, 1) == (int)gridDim.x - 1) {
            g_bar_count = 0;
            __threadfence();
            g_bar_gen = gen + 1;
        } else {
            while (g_bar_gen == gen) { }
        }
        __threadfence();
    }
    __syncthreads();
}

// ==== Single persistent kernel: prep (P0..P4) + fused final pipeline ====
__global__ __launch_bounds__(NTH, 2)
void k_all(const float* __restrict__ x,
           const float* __restrict__ bases,
           const float* __restrict__ comp,
           const float* __restrict__ root,
           const float* __restrict__ bias,
           const float* __restrict__ w1, const float* __restrict__ b1,
           const float* __restrict__ w2, const float* __restrict__ b2,
           const float* __restrict__ wp, const float* __restrict__ bp,
           const int* __restrict__ ei, const int* __restrict__ et,
           const int* __restrict__ ids, float* __restrict__ out) {
    const int tid  = threadIdx.x;
    const int gtid = blockIdx.x * NTH + tid;
    const int NT   = gridDim.x * NTH;
    const int lane = tid & 31;

    // ---- P0: init + weight concat ----
    for (int i = gtid; i < N_ENTITY; i += NT) g_map[i] = 0x7fffffff;
    for (int i = gtid; i < N_POS * N_REL; i += NT) g_deg[i] = 0;
    for (int i = gtid; i < KTOT * DD; i += NT)
        g_w[i] = (i < DD * DD) ? root[i] : bases[i - DD * DD];
    if (gtid == 0) { g_cnt = 0; g_zcnt = 0; }
    grid_bar();

    // ---- P1: scatter (min position canonical) ----
    if (gtid < N_POS) atomicMin(&g_map[ids[gtid]], gtid);
    grid_bar();

    // ---- P2: edge scan with warp-aggregated compaction atomics ----
    {
        const int NQUAD = NEDGE / 4;
        const int NITER = (NQUAD + NT - 1) / NT;   // 2
        for (int it = 0; it < NITER; ++it) {
            int t = gtid + it * NT;
            bool valid = t < NQUAD;
            int4 dst4 = valid ? reinterpret_cast<const int4*>(ei + NEDGE)[t]
                              : make_int4(0, 0, 0, 0);
            int ds[4] = {dst4.x, dst4.y, dst4.z, dst4.w};
#pragma unroll
            for (int q = 0; q < 4; ++q) {
                int slot = valid ? g_map[ds[q]] : 0x7fffffff;
                bool hit = slot < N_POS;
                unsigned m = __ballot_sync(0xffffffffu, hit);
                if (hit) {
                    int e = t * 4 + q;
                    int rel = __ldg(&et[e]);
                    int row = slot * N_REL + rel;
                    int old = atomicAdd(&g_deg[row], 1);
                    if (old == 1) {
                        int zp = atomicAdd(&g_zcnt, 1);
                        if (zp < ZMAX) g_zlist[zp] = row;
                    }
                    int leader = __ffs(m) - 1;
                    int rank = __popc(m & ((1u << lane) - 1u));
                    int base = 0;
                    if (lane == leader) base = atomicAdd(&g_cnt, __popc(m));
                    base = __shfl_sync(m, base, leader);
                    int p = base + rank;
                    if (p < CAP) g_ce[p] = make_int4(__ldg(&ei[e]), slot, rel, 0);
                }
            }
        }
    }
    grid_bar();

    // ---- P3: zero deg>=2 rows ----
    {
        int warp = gtid >> 5, nw = NT >> 5;
        int nz = *(volatile int*)&g_zcnt; if (nz > ZMAX) nz = ZMAX;
        float4 z = make_float4(0.f, 0.f, 0.f, 0.f);
        for (int i = warp; i < nz; i += nw) {
            int row = g_zlist[i];
            reinterpret_cast<float4*>(g_s + (size_t)row * DD)[lane] = z;
        }
    }
    grid_bar();

    // ---- P4: accumulate edges ----
    {
        int warp = gtid >> 5, nw = NT >> 5;
        int cnt = *(volatile int*)&g_cnt; if (cnt > CAP) cnt = CAP;
        for (int i = warp; i < cnt; i += nw) {
            int4 ce = g_ce[i];
            int row = ce.y * N_REL + ce.z;
            int dg = g_deg[row];
            float4 xv = reinterpret_cast<const float4*>(x + (long)ce.x * DD)[lane];
            float* sp = &g_s[(size_t)row * DD + lane * 4];
            if (dg == 1) {
                *reinterpret_cast<float4*>(sp) = xv;
            } else {
                atomicAdd(sp + 0, xv.x);
                atomicAdd(sp + 1, xv.y);
                atomicAdd(sp + 2, xv.z);
                atomicAdd(sp + 3, xv.w);
            }
        }
    }
    grid_bar();

    // ==== Final fused pipeline: blocks 0..255 handle TILE=4 positions each ====
    if (blockIdx.x >= N_POS / TILE) return;

    extern __shared__ float sm[];
    float* aT      = sm;                       // [KTOT][4] = 4608 floats
    float* compS   = aT + KTOT * TILE;         // 384
    float* hb      = compS + N_REL * NB;       // 512
    float* zb      = hb + TILE * DD;           // 256
    float* red     = zb + TILE * 64;           // 8192
    float* actNorm = red + 8192;               // 192
    int*   actRel  = (int*)(actNorm + TILE * N_REL);   // 192 ints
    int*   actCnt  = (int*)(actRel + TILE * N_REL);    // 4 ints
    int*   canon   = actCnt + TILE;            // 4 ints

    const int pbase = blockIdx.x * TILE;

    if (tid < TILE) canon[tid] = __ldcg(&g_map[ids[pbase + tid]]);
    {
        int p = tid >> 7, d = tid & 127;
        aT[d * TILE + p] = x[(long)ids[pbase + p] * DD + d];
    }
    if (tid < N_REL * NB) compS[tid] = comp[tid];
    __syncthreads();

    // build compacted active-relation lists: warp w -> position w
    if ((tid >> 5) < TILE) {
        int w = tid >> 5;
        int count = 0;
#pragma unroll
        for (int base = 0; base < 64; base += 32) {
            int r = base + lane;
            bool pred = false;
            float nm = 0.0f;
            if (r < N_REL) {
                int dg = __ldcg(&g_deg[canon[w] * N_REL + r]);
                if (dg > 0) { pred = true; nm = 1.0f / (float)dg; }
            }
            unsigned m = __ballot_sync(0xffffffffu, pred);
            if (pred) {
                int idx = count + __popc(m & ((1u << lane) - 1u));
                actRel[w * N_REL + idx] = r;
                actNorm[w * N_REL + idx] = nm;
            }
            count += __popc(m);
        }
        if (lane == 0) actCnt[w] = count;
    }
    __syncthreads();

    // phase 2: dense loop over active rels, unrolled x4, packed f32x2
    {
        const int pp = tid >> 7;
        const int d  = tid & 127;
        const float* srow = &g_s[(size_t)canon[pp] * N_REL * DD + d];
        const int* rl = actRel + pp * N_REL;
        const float* nl = actNorm + pp * N_REL;
        const int cnt = actCnt[pp];
        unsigned long long acc2[4] = {0ull, 0ull, 0ull, 0ull};
        int i = 0;
        for (; i + 4 <= cnt; i += 4) {
            float s0 = __ldcg(srow + rl[i + 0] * DD);
            float s1 = __ldcg(srow + rl[i + 1] * DD);
            float s2 = __ldcg(srow + rl[i + 2] * DD);
            float s3 = __ldcg(srow + rl[i + 3] * DD);
            s0 *= nl[i + 0]; s1 *= nl[i + 1]; s2 *= nl[i + 2]; s3 *= nl[i + 3];
            unsigned long long v0, v1, v2, v3;
            PACK_DUP(v0, s0); PACK_DUP(v1, s1); PACK_DUP(v2, s2); PACK_DUP(v3, s3);
            const unsigned long long* c0 =
                reinterpret_cast<const unsigned long long*>(compS + rl[i + 0] * NB);
            const unsigned long long* c1 =
                reinterpret_cast<const unsigned long long*>(compS + rl[i + 1] * NB);
            const unsigned long long* c2 =
                reinterpret_cast<const unsigned long long*>(compS + rl[i + 2] * NB);
            const unsigned long long* c3 =
                reinterpret_cast<const unsigned long long*>(compS + rl[i + 3] * NB);
#pragma unroll
            for (int k2 = 0; k2 < 4; ++k2) {
                FMA2(acc2[k2], v0, c0[k2]);
                FMA2(acc2[k2], v1, c1[k2]);
                FMA2(acc2[k2], v2, c2[k2]);
                FMA2(acc2[k2], v3, c3[k2]);
            }
        }
        for (; i < cnt; ++i) {
            float sv = __ldcg(srow + rl[i] * DD) * nl[i];
            unsigned long long sv2;
            PACK_DUP(sv2, sv);
            const unsigned long long* cp =
                reinterpret_cast<const unsigned long long*>(compS + rl[i] * NB);
#pragma unroll
            for (int k2 = 0; k2 < 4; ++k2) FMA2(acc2[k2], sv2, cp[k2]);
        }
#pragma unroll
        for (int k2 = 0; k2 < 4; ++k2) {
            unsigned int lo, hi;
            asm("mov.b64 {%0, %1}, %2;" : "=r"(lo), "=r"(hi) : "l"(acc2[k2]));
            aT[((2 * k2 + 1) * DD + d) * TILE + pp] = __uint_as_float(lo);
            aT[((2 * k2 + 2) * DD + d) * TILE + pp] = __uint_as_float(hi);
        }
    }
    __syncthreads();

    // phase 3: GEMM, 16 K-slices x 32 lanes, 4pos x 4col, FFMA2
    {
        const int kh = tid >> 5;
        const int c0 = (tid & 31) * 4;
        unsigned long long acc2[8];
#pragma unroll
        for (int i = 0; i < 8; ++i) acc2[i] = 0ull;

        const int r0 = kh * KSLICE;
        const float* Wb = g_w + (size_t)r0 * DD + c0;
        const float* Ab = aT + r0 * TILE;

        for (int ch = 0; ch < KSLICE; ch += 4) {
            ulonglong2 w[4];
#pragma unroll
            for (int t = 0; t < 4; ++t)
                w[t] = *reinterpret_cast<const ulonglong2*>(Wb + (size_t)(ch + t) * DD);
#pragma unroll
            for (int t = 0; t < 4; ++t) {
                float4 a = *reinterpret_cast<const float4*>(Ab + (ch + t) * TILE);
                unsigned long long ax, ay, az, aw;
                PACK_DUP(ax, a.x);
                PACK_DUP(ay, a.y);
                PACK_DUP(az, a.z);
                PACK_DUP(aw, a.w);
                FMA2(acc2[0], ax, w[t].x); FMA2(acc2[1], ax, w[t].y);
                FMA2(acc2[2], ay, w[t].x); FMA2(acc2[3], ay, w[t].y);
                FMA2(acc2[4], az, w[t].x); FMA2(acc2[5], az, w[t].y);
                FMA2(acc2[6], aw, w[t].x); FMA2(acc2[7], aw, w[t].y);
            }
        }
#pragma unroll
        for (int p = 0; p < TILE; ++p) {
            ulonglong2 v;
            v.x = acc2[p * 2]; v.y = acc2[p * 2 + 1];
            *reinterpret_cast<ulonglong2*>(red + kh * (TILE * DD) + p * DD + c0) = v;
        }
    }
    __syncthreads();

    // reduce 16 partials + bias + residual -> hb[pos][d]
    {
        int p = tid >> 7, d = tid & 127;
        float s = bias[d] + aT[d * TILE + p];
#pragma unroll
        for (int k = 0; k < NSLICE; ++k) s += red[k * (TILE * DD) + tid];
        hb[tid] = s;
    }
    __syncthreads();

    // stage w1
    {
        const float4* src = reinterpret_cast<const float4*>(w1);
        float4* dst = reinterpret_cast<float4*>(red);
#pragma unroll
        for (int t = 0; t < 4; ++t) dst[tid + t * 512] = src[tid + t * 512];
    }
    __syncthreads();

    // phase 5: zb[p][c] = relu(hb[p] @ w1 + b1)
    if (tid < TILE * 64) {
        int p = tid >> 6, c = tid & 63;
        float acc = b1[c];
        const float* wcol = red + c;
        const float4* h4 = reinterpret_cast<const float4*>(hb + p * DD);
#pragma unroll 4
        for (int j4 = 0; j4 < DD / 4; ++j4) {
            float w0 = wcol[(j4 * 4 + 0) * 64];
            float w1v = wcol[(j4 * 4 + 1) * 64];
            float w2v = wcol[(j4 * 4 + 2) * 64];
            float w3v = wcol[(j4 * 4 + 3) * 64];
            float4 h = h4[j4];
            acc += h.x * w0 + h.y * w1v + h.z * w2v + h.w * w3v;
        }
        zb[p * 64 + c] = fmaxf(acc, 0.0f);
    }
    __syncthreads();

    // stage w2
    {
        const float4* src = reinterpret_cast<const float4*>(w2);
        float4* dst = reinterpret_cast<float4*>(red);
#pragma unroll
        for (int t = 0; t < 4; ++t) dst[tid + t * 512] = src[tid + t * 512];
    }
    __syncthreads();

    // phase 6: hb[p][dd] += zb[p] @ w2 + b2
    {
        int p = tid >> 7, dd2 = tid & 127;
        float acc = b2[dd2] + hb[tid];
        const float* wcol = red + dd2;
        const float4* z4 = reinterpret_cast<const float4*>(zb + p * 64);
#pragma unroll 4
        for (int c4 = 0; c4 < 16; ++c4) {
            float w0 = wcol[(c4 * 4 + 0) * DD];
            float w1v = wcol[(c4 * 4 + 1) * DD];
            float w2v = wcol[(c4 * 4 + 2) * DD];
            float w3v = wcol[(c4 * 4 + 3) * DD];
            float4 z = z4[c4];
            acc += z.x * w0 + z.y * w1v + z.z * w2v + z.w * w3v;
        }
        hb[tid] = acc;
    }
    __syncthreads();

    // phase 7: out = hb @ wp + bp (1024 outputs, 2 pos/thread)
    {
        int o = tid & 255, ph = tid >> 8;
        int p0 = ph * 2;
        float b = bp[o];
        float acc0 = b, acc1 = b;
        const float* wcol = wp + o;
        const float4* h0 = reinterpret_cast<const float4*>(hb + p0 * DD);
        const float4* h1 = reinterpret_cast<const float4*>(hb + (p0 + 1) * DD);
#pragma unroll 4
        for (int j4 = 0; j4 < DD / 4; ++j4) {
            float w0 = wcol[(size_t)(j4 * 4 + 0) * HIDSZ];
            float w1v = wcol[(size_t)(j4 * 4 + 1) * HIDSZ];
            float w2v = wcol[(size_t)(j4 * 4 + 2) * HIDSZ];
            float w3v = wcol[(size_t)(j4 * 4 + 3) * HIDSZ];
            float4 a = h0[j4], c = h1[j4];
            acc0 += a.x * w0 + a.y * w1v + a.z * w2v + a.w * w3v;
            acc1 += c.x * w0 + c.y * w1v + c.z * w2v + c.w * w3v;
        }
        out[((long)(pbase + p0)) * HIDSZ + o] = acc0;
        out[((long)(pbase + p0 + 1)) * HIDSZ + o] = acc1;
    }
}

extern "C" void kernel_launch(void* const* d_in, const int* in_sizes, int n_in,
                              void* d_out, int out_size) {
    const float* node_embeds = (const float*)d_in[0];
    const float* bases       = (const float*)d_in[1];
    const float* comp        = (const float*)d_in[2];
    const float* root        = (const float*)d_in[3];
    const float* bias        = (const float*)d_in[4];
    const float* w1          = (const float*)d_in[5];
    const float* b1          = (const float*)d_in[6];
    const float* w2          = (const float*)d_in[7];
    const float* b2          = (const float*)d_in[8];
    const float* wp          = (const float*)d_in[9];
    const float* bp          = (const float*)d_in[10];
    const int*   edge_index  = (const int*)d_in[11];
    const int*   edge_type   = (const int*)d_in[12];
    const int*   entity_ids  = (const int*)d_in[13];
    float* out = (float*)d_out;

    const int smem_bytes = (KTOT * TILE + N_REL * NB + TILE * DD + TILE * 64 + 8192 +
                            TILE * N_REL) * 4 + (TILE * N_REL + 2 * TILE) * 4;
    cudaFuncSetAttribute(k_all, cudaFuncAttributeMaxDynamicSharedMemorySize, smem_bytes);

    k_all<<<GRID, NTH, smem_bytes>>>(node_embeds, bases, comp, root, bias,
                                     w1, b1, w2, b2, wp, bp,
                                     edge_index, edge_type, entity_ids, out);
    (void)in_sizes; (void)n_in; (void)out_size;
}